// round 1
// baseline (speedup 1.0000x reference)
#include <cuda_runtime.h>
#include <math.h>

// ---------------------------------------------------------------------------
// RNNCellModel: 4 coupled RNN cells, B=16, T=50.
// Strategy (round 1, correctness + sane baseline):
//   - One kernel per cell per timestep (200 launches, all default stream,
//     graph-capturable, dependency order preserved by stream ordering).
//   - Each cell: out[b,n] = tanh( sum_seg act_seg[b,:] . W_seg[n,:] + b_ih[n]+b_hh[n] )
//     where segments describe the concatenated input pieces + the recurrent term.
//   - Warp-per-neuron: 32 lanes stride over K in float4, 16 accumulators
//     (one per batch row), butterfly reduce, tanh, store.
//   - Hidden state at time t IS the output at time t -> read prev states
//     straight out of d_out (or the initial-h inputs for t==0). No scratch.
// ---------------------------------------------------------------------------

#define BB 16
#define TT 50
#define XX 3600
#define E4N 4800
#define I4N 1200
#define E23N 4800
#define I23N 1200
#define IN4E 13200
#define IN4I 16800
#define IN23E 6000
#define IN23I 9600

#define BDIM 256
#define WARPS 8

struct Seg {
    const float* act;   // activation base (batch row 0)
    const float* w;     // weight base (neuron row 0, segment col 0)
    int act_ld;         // elements between batch rows
    int w_ld;           // elements between neuron rows
    int len;            // segment length (multiple of 4)
};

struct CellArgs {
    Seg segs[5];
    int nseg;
    const float* b_ih;
    const float* b_hh;
    float* out;         // out[b,n] at out + b*out_ld + n
    int out_ld;
};

__global__ __launch_bounds__(BDIM) void cell_kernel(CellArgs a) {
    const int warp = threadIdx.x >> 5;
    const int lane = threadIdx.x & 31;
    const int n = blockIdx.x * WARPS + warp;

    float acc[BB];
#pragma unroll
    for (int b = 0; b < BB; ++b) acc[b] = 0.f;

    for (int s = 0; s < a.nseg; ++s) {
        const Seg sg = a.segs[s];
        const float* __restrict__ wrow = sg.w + (size_t)n * sg.w_ld;
        const float* __restrict__ act = sg.act;
        const int ld = sg.act_ld;
        const int len = sg.len;
        for (int k = lane * 4; k < len; k += 128) {
            const float4 w4 = *reinterpret_cast<const float4*>(wrow + k);
#pragma unroll
            for (int b = 0; b < BB; ++b) {
                const float4 x4 =
                    *reinterpret_cast<const float4*>(act + (size_t)b * ld + k);
                acc[b] = fmaf(w4.x, x4.x, acc[b]);
                acc[b] = fmaf(w4.y, x4.y, acc[b]);
                acc[b] = fmaf(w4.z, x4.z, acc[b]);
                acc[b] = fmaf(w4.w, x4.w, acc[b]);
            }
        }
    }

#pragma unroll
    for (int off = 16; off; off >>= 1)
#pragma unroll
        for (int b = 0; b < BB; ++b)
            acc[b] += __shfl_xor_sync(0xffffffffu, acc[b], off);

    if (lane < BB) {
        float v = 0.f;
#pragma unroll
        for (int b = 0; b < BB; ++b)
            if (lane == b) v = acc[b];
        const float bias = a.b_ih[n] + a.b_hh[n];
        a.out[(size_t)lane * a.out_ld + n] = tanhf(v + bias);
    }
}

static inline Seg mkseg(const float* act, int act_ld, const float* w, int w_ld,
                        int len) {
    Seg s;
    s.act = act; s.act_ld = act_ld; s.w = w; s.w_ld = w_ld; s.len = len;
    return s;
}

extern "C" void kernel_launch(void* const* d_in, const int* in_sizes, int n_in,
                              void* d_out, int out_size) {
    const float* x_on   = (const float*)d_in[0];
    const float* x_off  = (const float*)d_in[1];
    const float* h4e0   = (const float*)d_in[2];
    const float* h4i0   = (const float*)d_in[3];
    const float* h23e0  = (const float*)d_in[4];
    const float* h23i0  = (const float*)d_in[5];
    const float* Wih4e  = (const float*)d_in[6];
    const float* Whh4e  = (const float*)d_in[7];
    const float* bih4e  = (const float*)d_in[8];
    const float* bhh4e  = (const float*)d_in[9];
    const float* Wih4i  = (const float*)d_in[10];
    const float* Whh4i  = (const float*)d_in[11];
    const float* bih4i  = (const float*)d_in[12];
    const float* bhh4i  = (const float*)d_in[13];
    const float* Wih23e = (const float*)d_in[14];
    const float* Whh23e = (const float*)d_in[15];
    const float* bih23e = (const float*)d_in[16];
    const float* bhh23e = (const float*)d_in[17];
    const float* Wih23i = (const float*)d_in[18];
    const float* Whh23i = (const float*)d_in[19];
    const float* bih23i = (const float*)d_in[20];
    const float* bhh23i = (const float*)d_in[21];

    float* out = (float*)d_out;
    float* y4e  = out;                                    // [B,T,E4]
    float* y4i  = y4e  + (size_t)BB * TT * E4N;           // [B,T,I4]
    float* y23e = y4i  + (size_t)BB * TT * I4N;           // [B,T,E23]
    float* y23i = y23e + (size_t)BB * TT * E23N;          // [B,T,I23]

    for (int t = 0; t < TT; ++t) {
        // previous-state sources (t==0 -> initial h inputs)
        const float* p4e  = t ? (y4e  + (size_t)(t - 1) * E4N)  : h4e0;
        const int    l4e  = t ? TT * E4N  : E4N;
        const float* p4i  = t ? (y4i  + (size_t)(t - 1) * I4N)  : h4i0;
        const int    l4i  = t ? TT * I4N  : I4N;
        const float* p23e = t ? (y23e + (size_t)(t - 1) * E23N) : h23e0;
        const int    l23e = t ? TT * E23N : E23N;
        const float* p23i = t ? (y23i + (size_t)(t - 1) * I23N) : h23i0;
        const int    l23i = t ? TT * I23N : I23N;

        const float* xon_t  = x_on  + (size_t)t * XX;   // batch stride T*X
        const float* xoff_t = x_off + (size_t)t * XX;

        float* o4e  = y4e  + (size_t)t * E4N;
        float* o4i  = y4i  + (size_t)t * I4N;
        float* o23e = y23e + (size_t)t * E23N;
        float* o23i = y23i + (size_t)t * I23N;

        // ---- cell 4e: in = [x_on, x_off, h4i(t-1), h23e(t-1)], rec h4e(t-1)
        {
            CellArgs a;
            a.segs[0] = mkseg(xon_t,  TT * XX,  Wih4e + 0,            IN4E, XX);
            a.segs[1] = mkseg(xoff_t, TT * XX,  Wih4e + XX,           IN4E, XX);
            a.segs[2] = mkseg(p4i,    l4i,      Wih4e + 2 * XX,       IN4E, I4N);
            a.segs[3] = mkseg(p23e,   l23e,     Wih4e + 2 * XX + I4N, IN4E, E23N);
            a.segs[4] = mkseg(p4e,    l4e,      Whh4e,                E4N,  E4N);
            a.nseg = 5; a.b_ih = bih4e; a.b_hh = bhh4e;
            a.out = o4e; a.out_ld = TT * E4N;
            cell_kernel<<<E4N / WARPS, BDIM>>>(a);
        }
        // ---- cell 4i: in = [x_on, x_off, h4e(t)!, h23e(t-1)], rec h4i(t-1)
        {
            CellArgs a;
            a.segs[0] = mkseg(xon_t,  TT * XX,  Wih4i + 0,            IN4I, XX);
            a.segs[1] = mkseg(xoff_t, TT * XX,  Wih4i + XX,           IN4I, XX);
            a.segs[2] = mkseg(o4e,    TT * E4N, Wih4i + 2 * XX,       IN4I, E4N);
            a.segs[3] = mkseg(p23e,   l23e,     Wih4i + 2 * XX + E4N, IN4I, E23N);
            a.segs[4] = mkseg(p4i,    l4i,      Whh4i,                I4N,  I4N);
            a.nseg = 5; a.b_ih = bih4i; a.b_hh = bhh4i;
            a.out = o4i; a.out_ld = TT * I4N;
            cell_kernel<<<I4N / WARPS, BDIM>>>(a);
        }
        // ---- cell 23e: in = [h4e(t)!, h23i(t-1)], rec h23e(t-1)
        {
            CellArgs a;
            a.segs[0] = mkseg(o4e,  TT * E4N, Wih23e + 0,   IN23E, E4N);
            a.segs[1] = mkseg(p23i, l23i,     Wih23e + E4N, IN23E, I23N);
            a.segs[2] = mkseg(p23e, l23e,     Whh23e,       E23N,  E23N);
            a.nseg = 3; a.b_ih = bih23e; a.b_hh = bhh23e;
            a.out = o23e; a.out_ld = TT * E23N;
            cell_kernel<<<E23N / WARPS, BDIM>>>(a);
        }
        // ---- cell 23i: in = [h4e(t)!, h23e(t)!], rec h23i(t-1)
        {
            CellArgs a;
            a.segs[0] = mkseg(o4e,  TT * E4N,  Wih23i + 0,   IN23I, E4N);
            a.segs[1] = mkseg(o23e, TT * E23N, Wih23i + E4N, IN23I, E23N);
            a.segs[2] = mkseg(p23i, l23i,      Whh23i,       I23N,  I23N);
            a.nseg = 3; a.b_ih = bih23i; a.b_hh = bhh23i;
            a.out = o23i; a.out_ld = TT * I23N;
            cell_kernel<<<I23N / WARPS, BDIM>>>(a);
        }
    }
    (void)in_sizes; (void)n_in; (void)out_size;
}

// round 3
// speedup vs baseline: 2.3793x; 2.3793x over previous
#include <cuda_runtime.h>
#include <math.h>

// ---------------------------------------------------------------------------
// Round 3 (resubmit of R2 design with de-risking):
// thread-per-neuron GEMV-T, smem-broadcast activations, f32x2 packed FMAs,
// transposed+pair-packed weights (streamed with __ldcs), split-K + reduce.
//
// y[b,n] = tanh( sum_k act[b,k] * W[n,k] + b_ih[n] + b_hh[n] )
// ---------------------------------------------------------------------------

#define BB 16
#define TT 50
#define XX 3600
#define E4N 4800
#define I4N 1200
#define E23N 4800
#define I23N 1200
#define IN4E 13200
#define IN4I 16800
#define IN23E 6000
#define IN23I 9600

#define CHUNK 128            // k-floats per staged chunk
#define GBDIM 128            // threads per gemvt block
#define NPB 256              // neurons per block (2 per thread)

#define S4E  30
#define S4I  72
#define S23E 30
#define S23I 72

// WT layout offsets (float2 units)
#define OFF4E  0ull
#define OFF4I  43200000ull
#define OFF23E 54000000ull
#define OFF23I 79920000ull

__device__ float2 g_WT[86400000];     // 691.2 MB transposed pair-packed weights
__device__ float  g_partial[2400000]; // split-K partials (max 30*16*4800)

__device__ __forceinline__ void fma2(unsigned long long& d,
                                     unsigned long long a,
                                     unsigned long long b) {
    asm("fma.rn.f32x2 %0, %1, %2, %0;" : "+l"(d) : "l"(a), "l"(b));
}

// ---- transpose W[N][K] (row-major) -> out[k/2][N] float2 k-pairs ----------
__global__ __launch_bounds__(256) void transpose_kernel(
    const float* __restrict__ W, float2* __restrict__ out, int K, int N) {
    __shared__ float tile[64][17];
    const int k0 = blockIdx.x * 16;
    const int n0 = blockIdx.y * 64;
    const int t = threadIdx.x;
    const int row = t >> 2;
    const int kk = (t & 3) * 4;
    if (n0 + row < N) {
        const float4 v = *reinterpret_cast<const float4*>(
            W + (size_t)(n0 + row) * K + k0 + kk);
        tile[row][kk] = v.x; tile[row][kk + 1] = v.y;
        tile[row][kk + 2] = v.z; tile[row][kk + 3] = v.w;
    }
    __syncthreads();
    const int k2 = t >> 5;   // 0..7
    const int n = t & 31;
#pragma unroll
    for (int h = 0; h < 2; ++h) {
        const int nn = n + h * 32;
        if (n0 + nn < N)
            out[(size_t)(k0 / 2 + k2) * N + n0 + nn] =
                make_float2(tile[nn][2 * k2], tile[nn][2 * k2 + 1]);
    }
}

// ---- main GEMV-T ----------------------------------------------------------
struct GArgs {
    const float2* wt;        // [Ktot/2][N] pairs
    const float* act[5];     // activation segment bases (batch row 0)
    int ld[5];               // batch stride (elements)
    int len[5];              // segment length (floats, multiple of 4)
    int nseg;
    int N;
    int S;
    float* partial;          // [S][16][N]
};

__global__ __launch_bounds__(GBDIM, 2) void gemvt_kernel(GArgs a) {
    __shared__ float4 s_act[BB][CHUNK / 4];
    const int t = threadIdx.x;
    const int n0 = blockIdx.x * NPB + t;
    const int n1 = n0 + GBDIM;
    const int s = blockIdx.y;
    const bool g0 = n0 < a.N;
    const bool g1 = n1 < a.N;
    const int m0 = g0 ? n0 : 0;
    const int m1 = g1 ? n1 : 0;

    unsigned long long acc0[BB], acc1[BB];
#pragma unroll
    for (int b = 0; b < BB; ++b) { acc0[b] = 0ull; acc1[b] = 0ull; }

    const unsigned long long* __restrict__ wtu =
        reinterpret_cast<const unsigned long long*>(a.wt);
    const int NN = a.N;
    const int S = a.S;

    int gc = 0;      // global chunk counter across segments
    int koff2 = 0;   // pair-row offset of current segment in WT
    for (int sg = 0; sg < a.nseg; ++sg) {
        const float* __restrict__ ap = a.act[sg];
        const int ld = a.ld[sg];
        const int len = a.len[sg];
        const int nch = (len + CHUNK - 1) / CHUNK;
        for (int ch = 0; ch < nch; ++ch, ++gc) {
            if (gc % S != s) continue;
            const int k0 = ch * CHUNK;
            const int clen = min(CHUNK, len - k0);   // multiple of 4
            const int nf4 = clen >> 2;
            __syncthreads();
            for (int i = t; i < nf4 * BB; i += GBDIM) {
                const int b = i / nf4;
                const int j = i - b * nf4;
                s_act[b][j] = *reinterpret_cast<const float4*>(
                    ap + (size_t)b * ld + k0 + j * 4);
            }
            __syncthreads();
            const unsigned long long* wp =
                wtu + (size_t)(koff2 + (k0 >> 1)) * NN;
            const unsigned long long* wp0 = wp + m0;
            const unsigned long long* wp1 = wp + m1;
            const int np = clen >> 2;  // float4 steps (2 pair-rows each)
#pragma unroll 2
            for (int q = 0; q < np; ++q) {
                const unsigned long long wa0 = __ldcs(wp0);
                const unsigned long long wa1 = __ldcs(wp1);
                const unsigned long long wb0 = __ldcs(wp0 + NN);
                const unsigned long long wb1 = __ldcs(wp1 + NN);
                wp0 += 2 * NN;
                wp1 += 2 * NN;
#pragma unroll
                for (int b = 0; b < BB; ++b) {
                    const ulonglong2 av =
                        reinterpret_cast<const ulonglong2*>(s_act[b])[q];
                    fma2(acc0[b], wa0, av.x);
                    fma2(acc1[b], wa1, av.x);
                    fma2(acc0[b], wb0, av.y);
                    fma2(acc1[b], wb1, av.y);
                }
            }
        }
        koff2 += len >> 1;
    }

#pragma unroll
    for (int b = 0; b < BB; ++b) {
        const float2 f0 = *reinterpret_cast<const float2*>(&acc0[b]);
        const float2 f1 = *reinterpret_cast<const float2*>(&acc1[b]);
        float* dst = a.partial + ((size_t)s * BB + b) * NN;
        if (g0) dst[n0] = f0.x + f0.y;
        if (g1) dst[n1] = f1.x + f1.y;
    }
}

// ---- reduce: sum splits + bias + tanh ------------------------------------
__global__ __launch_bounds__(256) void reduce_kernel(
    const float* __restrict__ partial, const float* __restrict__ bih,
    const float* __restrict__ bhh, float* __restrict__ out,
    int N, int S, int out_ld) {
    const int idx = blockIdx.x * 256 + threadIdx.x;
    if (idx >= BB * N) return;
    const int n = idx % N;
    const int b = idx / N;
    float sum = bih[n] + bhh[n];
    for (int s = 0; s < S; ++s)
        sum += partial[((size_t)s * BB + b) * N + n];
    out[(size_t)b * out_ld + n] = tanhf(sum);
}

// ---------------------------------------------------------------------------
extern "C" void kernel_launch(void* const* d_in, const int* in_sizes, int n_in,
                              void* d_out, int out_size) {
    const float* x_on   = (const float*)d_in[0];
    const float* x_off  = (const float*)d_in[1];
    const float* h4e0   = (const float*)d_in[2];
    const float* h4i0   = (const float*)d_in[3];
    const float* h23e0  = (const float*)d_in[4];
    const float* h23i0  = (const float*)d_in[5];
    const float* Wih4e  = (const float*)d_in[6];
    const float* Whh4e  = (const float*)d_in[7];
    const float* bih4e  = (const float*)d_in[8];
    const float* bhh4e  = (const float*)d_in[9];
    const float* Wih4i  = (const float*)d_in[10];
    const float* Whh4i  = (const float*)d_in[11];
    const float* bih4i  = (const float*)d_in[12];
    const float* bhh4i  = (const float*)d_in[13];
    const float* Wih23e = (const float*)d_in[14];
    const float* Whh23e = (const float*)d_in[15];
    const float* bih23e = (const float*)d_in[16];
    const float* bhh23e = (const float*)d_in[17];
    const float* Wih23i = (const float*)d_in[18];
    const float* Whh23i = (const float*)d_in[19];
    const float* bih23i = (const float*)d_in[20];
    const float* bhh23i = (const float*)d_in[21];

    float2* wtp = 0;
    float* pp = 0;
    cudaGetSymbolAddress((void**)&wtp, g_WT);
    cudaGetSymbolAddress((void**)&pp, g_partial);

    // ---- per-replay weight transposes ----
    transpose_kernel<<<dim3(IN4E / 16, (E4N + 63) / 64), 256>>>(
        Wih4e, wtp + OFF4E, IN4E, E4N);
    transpose_kernel<<<dim3(E4N / 16, (E4N + 63) / 64), 256>>>(
        Whh4e, wtp + OFF4E + (size_t)(IN4E / 2) * E4N, E4N, E4N);
    transpose_kernel<<<dim3(IN4I / 16, (I4N + 63) / 64), 256>>>(
        Wih4i, wtp + OFF4I, IN4I, I4N);
    transpose_kernel<<<dim3(I4N / 16, (I4N + 63) / 64), 256>>>(
        Whh4i, wtp + OFF4I + (size_t)(IN4I / 2) * I4N, I4N, I4N);
    transpose_kernel<<<dim3(IN23E / 16, (E23N + 63) / 64), 256>>>(
        Wih23e, wtp + OFF23E, IN23E, E23N);
    transpose_kernel<<<dim3(E23N / 16, (E23N + 63) / 64), 256>>>(
        Whh23e, wtp + OFF23E + (size_t)(IN23E / 2) * E23N, E23N, E23N);
    transpose_kernel<<<dim3(IN23I / 16, (I23N + 63) / 64), 256>>>(
        Wih23i, wtp + OFF23I, IN23I, I23N);
    transpose_kernel<<<dim3(I23N / 16, (I23N + 63) / 64), 256>>>(
        Whh23i, wtp + OFF23I + (size_t)(IN23I / 2) * I23N, I23N, I23N);

    float* out = (float*)d_out;
    float* y4e  = out;                             // [B,T,E4]
    float* y4i  = y4e  + (size_t)BB * TT * E4N;    // [B,T,I4]
    float* y23e = y4i  + (size_t)BB * TT * I4N;    // [B,T,E23]
    float* y23i = y23e + (size_t)BB * TT * E23N;   // [B,T,I23]

    const int nbE = (E4N + NPB - 1) / NPB;   // 19
    const int nbI = (I4N + NPB - 1) / NPB;   // 5

    for (int t = 0; t < TT; ++t) {
        const float* p4e  = t ? (y4e  + (size_t)(t - 1) * E4N)  : h4e0;
        const int    l4e  = t ? TT * E4N  : E4N;
        const float* p4i  = t ? (y4i  + (size_t)(t - 1) * I4N)  : h4i0;
        const int    l4i  = t ? TT * I4N  : I4N;
        const float* p23e = t ? (y23e + (size_t)(t - 1) * E23N) : h23e0;
        const int    l23e = t ? TT * E23N : E23N;
        const float* p23i = t ? (y23i + (size_t)(t - 1) * I23N) : h23i0;
        const int    l23i = t ? TT * I23N : I23N;

        const float* xon_t  = x_on  + (size_t)t * XX;
        const float* xoff_t = x_off + (size_t)t * XX;

        float* o4e  = y4e  + (size_t)t * E4N;
        float* o4i  = y4i  + (size_t)t * I4N;
        float* o23e = y23e + (size_t)t * E23N;
        float* o23i = y23i + (size_t)t * I23N;

        // ---- cell 4e: [x_on, x_off, h4i(t-1), h23e(t-1)] + hh h4e(t-1)
        {
            GArgs a;
            a.wt = wtp + OFF4E; a.N = E4N; a.S = S4E; a.partial = pp;
            a.act[0] = xon_t;  a.ld[0] = TT * XX;  a.len[0] = XX;
            a.act[1] = xoff_t; a.ld[1] = TT * XX;  a.len[1] = XX;
            a.act[2] = p4i;    a.ld[2] = l4i;      a.len[2] = I4N;
            a.act[3] = p23e;   a.ld[3] = l23e;     a.len[3] = E23N;
            a.act[4] = p4e;    a.ld[4] = l4e;      a.len[4] = E4N;
            a.nseg = 5;
            gemvt_kernel<<<dim3(nbE, S4E), GBDIM>>>(a);
            reduce_kernel<<<(BB * E4N + 255) / 256, 256>>>(
                pp, bih4e, bhh4e, o4e, E4N, S4E, TT * E4N);
        }
        // ---- cell 4i: [x_on, x_off, h4e(t), h23e(t-1)] + hh h4i(t-1)
        {
            GArgs a;
            a.wt = wtp + OFF4I; a.N = I4N; a.S = S4I; a.partial = pp;
            a.act[0] = xon_t;  a.ld[0] = TT * XX;  a.len[0] = XX;
            a.act[1] = xoff_t; a.ld[1] = TT * XX;  a.len[1] = XX;
            a.act[2] = o4e;    a.ld[2] = TT * E4N; a.len[2] = E4N;
            a.act[3] = p23e;   a.ld[3] = l23e;     a.len[3] = E23N;
            a.act[4] = p4i;    a.ld[4] = l4i;      a.len[4] = I4N;
            a.nseg = 5;
            gemvt_kernel<<<dim3(nbI, S4I), GBDIM>>>(a);
            reduce_kernel<<<(BB * I4N + 255) / 256, 256>>>(
                pp, bih4i, bhh4i, o4i, I4N, S4I, TT * I4N);
        }
        // ---- cell 23e: [h4e(t), h23i(t-1)] + hh h23e(t-1)
        {
            GArgs a;
            a.wt = wtp + OFF23E; a.N = E23N; a.S = S23E; a.partial = pp;
            a.act[0] = o4e;  a.ld[0] = TT * E4N; a.len[0] = E4N;
            a.act[1] = p23i; a.ld[1] = l23i;     a.len[1] = I23N;
            a.act[2] = p23e; a.ld[2] = l23e;     a.len[2] = E23N;
            a.nseg = 3;
            gemvt_kernel<<<dim3(nbE, S23E), GBDIM>>>(a);
            reduce_kernel<<<(BB * E23N + 255) / 256, 256>>>(
                pp, bih23e, bhh23e, o23e, E23N, S23E, TT * E23N);
        }
        // ---- cell 23i: [h4e(t), h23e(t)] + hh h23i(t-1)
        {
            GArgs a;
            a.wt = wtp + OFF23I; a.N = I23N; a.S = S23I; a.partial = pp;
            a.act[0] = o4e;  a.ld[0] = TT * E4N;  a.len[0] = E4N;
            a.act[1] = o23e; a.ld[1] = TT * E23N; a.len[1] = E23N;
            a.act[2] = p23i; a.ld[2] = l23i;      a.len[2] = I23N;
            a.nseg = 3;
            gemvt_kernel<<<dim3(nbI, S23I), GBDIM>>>(a);
            reduce_kernel<<<(BB * I23N + 255) / 256, 256>>>(
                pp, bih23i, bhh23i, o23i, I23N, S23I, TT * I23N);
        }
    }
    (void)in_sizes; (void)n_in; (void)out_size;
}

// round 4
// speedup vs baseline: 3.1209x; 1.3117x over previous
#include <cuda_runtime.h>
#include <math.h>
#include <stdint.h>

// ---------------------------------------------------------------------------
// Round 4: thread-per-neuron GEMV-T, smem-broadcast activations staged via
// double-buffered cp.async, float4-packed transposed weights streamed with
// __ldcs, f32x2 FMAs, split-K + vectorized reduce.
// ---------------------------------------------------------------------------

#define BB 16
#define TT 50
#define XX 3600
#define E4N 4800
#define I4N 1200
#define E23N 4800
#define I23N 1200
#define IN4E 13200
#define IN4I 16800
#define IN23E 6000
#define IN23I 9600

#define CHUNK 128            // k-floats per staged chunk
#define GBDIM 128            // threads per gemvt block (= neurons per block)

#define S4E  16
#define S4I  60
#define S23E 16
#define S23I 60

// WT layout offsets (float4 units)
#define OFF4E  0ull
#define OFF4I  21600000ull
#define OFF23E 27000000ull
#define OFF23I 39960000ull

__device__ float4 g_WT[43200000];     // 691.2 MB float4-packed transposed weights
__device__ float  g_partial[2400000]; // split-K partials

#define MAXCH 10

__device__ __forceinline__ void fma2(unsigned long long& d,
                                     unsigned long long a,
                                     unsigned long long b) {
    asm("fma.rn.f32x2 %0, %1, %2, %0;" : "+l"(d) : "l"(a), "l"(b));
}

// ---- transpose W[N][K] (row-major) -> out[k/4][N] float4 k-quads ----------
__global__ __launch_bounds__(256) void transpose_kernel(
    const float* __restrict__ W, float4* __restrict__ out, int K, int N) {
    __shared__ float tile[64][17];
    const int k0 = blockIdx.x * 16;
    const int n0 = blockIdx.y * 64;
    const int t = threadIdx.x;
    const int row = t >> 2;
    const int kk = (t & 3) * 4;
    if (n0 + row < N) {
        const float4 v = *reinterpret_cast<const float4*>(
            W + (size_t)(n0 + row) * K + k0 + kk);
        tile[row][kk] = v.x; tile[row][kk + 1] = v.y;
        tile[row][kk + 2] = v.z; tile[row][kk + 3] = v.w;
    }
    __syncthreads();
    const int k4l = t >> 6;   // 0..3
    const int n = t & 63;
    if (n0 + n < N)
        out[(size_t)(k0 / 4 + k4l) * N + n0 + n] =
            make_float4(tile[n][4 * k4l], tile[n][4 * k4l + 1],
                        tile[n][4 * k4l + 2], tile[n][4 * k4l + 3]);
}

// ---- main GEMV-T ----------------------------------------------------------
struct GArgs {
    const float4* wt;        // [Ktot/4][N] quads
    const float* act[5];     // activation segment bases (batch row 0)
    int ld[5];               // batch stride (elements)
    int len[5];              // segment length (floats, multiple of 16)
    int seg4off[5];          // cumulative float4-row offset of segment
    int nseg;
    int N;
    int S;
    float* partial;          // [S][16][N]
};

__global__ __launch_bounds__(GBDIM, 4) void gemvt_kernel(GArgs a) {
    __shared__ float4 s_act[2][BB][CHUNK / 4];   // 2 x 8KB
    const int t = threadIdx.x;
    const int n = blockIdx.x * GBDIM + t;
    const int s = blockIdx.y;
    const bool gok = n < a.N;
    const int m = gok ? n : 0;
    const int NN = a.N;

    // ---- collect this block's chunk descriptors (uniform across block) ----
    const float* dap[MAXCH];
    int dld[MAXCH], dk0[MAXCH], dcl[MAXCH], dw4[MAXCH];
    int nd = 0, gc = 0;
    for (int sg = 0; sg < a.nseg; ++sg) {
        const int len = a.len[sg];
        const int nch = (len + CHUNK - 1) / CHUNK;
        for (int ch = 0; ch < nch; ++ch, ++gc) {
            if (gc % a.S != s) continue;
            dap[nd] = a.act[sg];
            dld[nd] = a.ld[sg];
            dk0[nd] = ch * CHUNK;
            dcl[nd] = min(CHUNK, len - ch * CHUNK);
            dw4[nd] = a.seg4off[sg] + ((ch * CHUNK) >> 2);
            ++nd;
        }
    }

    unsigned long long acc[BB];
#pragma unroll
    for (int b = 0; b < BB; ++b) acc[b] = 0ull;

    // ---- stage chunk i into buffer buf via cp.async ----
    auto stage = [&](int i, int buf) {
        const float* __restrict__ ap = dap[i];
        const int nf4 = dcl[i] >> 2;
        const int k0 = dk0[i];
        const int ld = dld[i];
        for (int x = t; x < nf4 * BB; x += GBDIM) {
            const int b = x / nf4;
            const int j = x - b * nf4;
            const float* src = ap + (size_t)b * ld + k0 + 4 * j;
            uint32_t dst =
                (uint32_t)__cvta_generic_to_shared(&s_act[buf][b][j]);
            asm volatile("cp.async.cg.shared.global [%0], [%1], 16;"
                         :: "r"(dst), "l"(src));
        }
        asm volatile("cp.async.commit_group;");
    };

    // ---- compute chunk i from buffer buf ----
    auto compute = [&](int i, int buf) {
        const int np = dcl[i] >> 2;
        const float4* __restrict__ wp = a.wt + (size_t)dw4[i] * NN + m;
#pragma unroll 4
        for (int q = 0; q < np; ++q) {
            const float4 w = __ldcs(wp);
            wp += NN;
            const ulonglong2 wv = *reinterpret_cast<const ulonglong2*>(&w);
#pragma unroll
            for (int b = 0; b < BB; ++b) {
                const ulonglong2 av =
                    *reinterpret_cast<const ulonglong2*>(&s_act[buf][b][q]);
                fma2(acc[b], wv.x, av.x);
                fma2(acc[b], wv.y, av.y);
            }
        }
    };

    stage(0, 0);
    for (int i = 0; i < nd; ++i) {
        if (i + 1 < nd) {
            stage(i + 1, (i + 1) & 1);
            asm volatile("cp.async.wait_group 1;");
        } else {
            asm volatile("cp.async.wait_group 0;");
        }
        __syncthreads();
        compute(i, i & 1);
        __syncthreads();
    }

    if (gok) {
#pragma unroll
        for (int b = 0; b < BB; ++b) {
            const float2 f = *reinterpret_cast<const float2*>(&acc[b]);
            a.partial[((size_t)s * BB + b) * NN + n] = f.x + f.y;
        }
    }
}

// ---- reduce: sum splits + bias + tanh (float4) ---------------------------
__global__ __launch_bounds__(256) void reduce_kernel(
    const float4* __restrict__ partial, const float4* __restrict__ bih,
    const float4* __restrict__ bhh, float* __restrict__ out,
    int N4, int S, int out_ld) {
    const int idx = blockIdx.x * 256 + threadIdx.x;
    if (idx >= BB * N4) return;
    const int n4 = idx % N4;
    const int b = idx / N4;
    const float4 bi = bih[n4];
    const float4 bh = bhh[n4];
    float4 sum = make_float4(bi.x + bh.x, bi.y + bh.y,
                             bi.z + bh.z, bi.w + bh.w);
    for (int s = 0; s < S; ++s) {
        const float4 p = partial[((size_t)s * BB + b) * N4 + n4];
        sum.x += p.x; sum.y += p.y; sum.z += p.z; sum.w += p.w;
    }
    float4 r = make_float4(tanhf(sum.x), tanhf(sum.y),
                           tanhf(sum.z), tanhf(sum.w));
    *reinterpret_cast<float4*>(out + (size_t)b * out_ld + 4 * n4) = r;
}

// ---------------------------------------------------------------------------
extern "C" void kernel_launch(void* const* d_in, const int* in_sizes, int n_in,
                              void* d_out, int out_size) {
    const float* x_on   = (const float*)d_in[0];
    const float* x_off  = (const float*)d_in[1];
    const float* h4e0   = (const float*)d_in[2];
    const float* h4i0   = (const float*)d_in[3];
    const float* h23e0  = (const float*)d_in[4];
    const float* h23i0  = (const float*)d_in[5];
    const float* Wih4e  = (const float*)d_in[6];
    const float* Whh4e  = (const float*)d_in[7];
    const float* bih4e  = (const float*)d_in[8];
    const float* bhh4e  = (const float*)d_in[9];
    const float* Wih4i  = (const float*)d_in[10];
    const float* Whh4i  = (const float*)d_in[11];
    const float* bih4i  = (const float*)d_in[12];
    const float* bhh4i  = (const float*)d_in[13];
    const float* Wih23e = (const float*)d_in[14];
    const float* Whh23e = (const float*)d_in[15];
    const float* bih23e = (const float*)d_in[16];
    const float* bhh23e = (const float*)d_in[17];
    const float* Wih23i = (const float*)d_in[18];
    const float* Whh23i = (const float*)d_in[19];
    const float* bih23i = (const float*)d_in[20];
    const float* bhh23i = (const float*)d_in[21];

    float4* wtp = 0;
    float* pp = 0;
    cudaGetSymbolAddress((void**)&wtp, g_WT);
    cudaGetSymbolAddress((void**)&pp, g_partial);

    // ---- per-replay weight transposes (float4 pack) ----
    transpose_kernel<<<dim3(IN4E / 16, E4N / 64), 256>>>(
        Wih4e, wtp + OFF4E, IN4E, E4N);
    transpose_kernel<<<dim3(E4N / 16, E4N / 64), 256>>>(
        Whh4e, wtp + OFF4E + (size_t)(IN4E / 4) * E4N, E4N, E4N);
    transpose_kernel<<<dim3(IN4I / 16, (I4N + 63) / 64), 256>>>(
        Wih4i, wtp + OFF4I, IN4I, I4N);
    transpose_kernel<<<dim3(I4N / 16, (I4N + 63) / 64), 256>>>(
        Whh4i, wtp + OFF4I + (size_t)(IN4I / 4) * I4N, I4N, I4N);
    transpose_kernel<<<dim3(IN23E / 16, E23N / 64), 256>>>(
        Wih23e, wtp + OFF23E, IN23E, E23N);
    transpose_kernel<<<dim3(E23N / 16, E23N / 64), 256>>>(
        Whh23e, wtp + OFF23E + (size_t)(IN23E / 4) * E23N, E23N, E23N);
    transpose_kernel<<<dim3(IN23I / 16, (I23N + 63) / 64), 256>>>(
        Wih23i, wtp + OFF23I, IN23I, I23N);
    transpose_kernel<<<dim3(I23N / 16, (I23N + 63) / 64), 256>>>(
        Whh23i, wtp + OFF23I + (size_t)(IN23I / 4) * I23N, I23N, I23N);

    float* out = (float*)d_out;
    float* y4e  = out;                             // [B,T,E4]
    float* y4i  = y4e  + (size_t)BB * TT * E4N;    // [B,T,I4]
    float* y23e = y4i  + (size_t)BB * TT * I4N;    // [B,T,E23]
    float* y23i = y23e + (size_t)BB * TT * E23N;   // [B,T,I23]

    const int nbE = (E4N + GBDIM - 1) / GBDIM;   // 38
    const int nbI = (I4N + GBDIM - 1) / GBDIM;   // 10

    for (int t = 0; t < TT; ++t) {
        const float* p4e  = t ? (y4e  + (size_t)(t - 1) * E4N)  : h4e0;
        const int    l4e  = t ? TT * E4N  : E4N;
        const float* p4i  = t ? (y4i  + (size_t)(t - 1) * I4N)  : h4i0;
        const int    l4i  = t ? TT * I4N  : I4N;
        const float* p23e = t ? (y23e + (size_t)(t - 1) * E23N) : h23e0;
        const int    l23e = t ? TT * E23N : E23N;
        const float* p23i = t ? (y23i + (size_t)(t - 1) * I23N) : h23i0;
        const int    l23i = t ? TT * I23N : I23N;

        const float* xon_t  = x_on  + (size_t)t * XX;
        const float* xoff_t = x_off + (size_t)t * XX;

        float* o4e  = y4e  + (size_t)t * E4N;
        float* o4i  = y4i  + (size_t)t * I4N;
        float* o23e = y23e + (size_t)t * E23N;
        float* o23i = y23i + (size_t)t * I23N;

        // ---- cell 4e: [x_on, x_off, h4i(t-1), h23e(t-1)] + hh h4e(t-1)
        {
            GArgs a;
            a.wt = wtp + OFF4E; a.N = E4N; a.S = S4E; a.partial = pp;
            a.act[0] = xon_t;  a.ld[0] = TT * XX;  a.len[0] = XX;   a.seg4off[0] = 0;
            a.act[1] = xoff_t; a.ld[1] = TT * XX;  a.len[1] = XX;   a.seg4off[1] = 900;
            a.act[2] = p4i;    a.ld[2] = l4i;      a.len[2] = I4N;  a.seg4off[2] = 1800;
            a.act[3] = p23e;   a.ld[3] = l23e;     a.len[3] = E23N; a.seg4off[3] = 2100;
            a.act[4] = p4e;    a.ld[4] = l4e;      a.len[4] = E4N;  a.seg4off[4] = 3300;
            a.nseg = 5;
            gemvt_kernel<<<dim3(nbE, S4E), GBDIM>>>(a);
            reduce_kernel<<<(BB * E4N / 4 + 255) / 256, 256>>>(
                (const float4*)pp, (const float4*)bih4e, (const float4*)bhh4e,
                o4e, E4N / 4, S4E, TT * E4N);
        }
        // ---- cell 4i: [x_on, x_off, h4e(t), h23e(t-1)] + hh h4i(t-1)
        {
            GArgs a;
            a.wt = wtp + OFF4I; a.N = I4N; a.S = S4I; a.partial = pp;
            a.act[0] = xon_t;  a.ld[0] = TT * XX;  a.len[0] = XX;   a.seg4off[0] = 0;
            a.act[1] = xoff_t; a.ld[1] = TT * XX;  a.len[1] = XX;   a.seg4off[1] = 900;
            a.act[2] = o4e;    a.ld[2] = TT * E4N; a.len[2] = E4N;  a.seg4off[2] = 1800;
            a.act[3] = p23e;   a.ld[3] = l23e;     a.len[3] = E23N; a.seg4off[3] = 3000;
            a.act[4] = p4i;    a.ld[4] = l4i;      a.len[4] = I4N;  a.seg4off[4] = 4200;
            a.nseg = 5;
            gemvt_kernel<<<dim3(nbI, S4I), GBDIM>>>(a);
            reduce_kernel<<<(BB * I4N / 4 + 255) / 256, 256>>>(
                (const float4*)pp, (const float4*)bih4i, (const float4*)bhh4i,
                o4i, I4N / 4, S4I, TT * I4N);
        }
        // ---- cell 23e: [h4e(t), h23i(t-1)] + hh h23e(t-1)
        {
            GArgs a;
            a.wt = wtp + OFF23E; a.N = E23N; a.S = S23E; a.partial = pp;
            a.act[0] = o4e;  a.ld[0] = TT * E4N; a.len[0] = E4N;  a.seg4off[0] = 0;
            a.act[1] = p23i; a.ld[1] = l23i;     a.len[1] = I23N; a.seg4off[1] = 1200;
            a.act[2] = p23e; a.ld[2] = l23e;     a.len[2] = E23N; a.seg4off[2] = 1500;
            a.nseg = 3;
            gemvt_kernel<<<dim3(nbE, S23E), GBDIM>>>(a);
            reduce_kernel<<<(BB * E23N / 4 + 255) / 256, 256>>>(
                (const float4*)pp, (const float4*)bih23e, (const float4*)bhh23e,
                o23e, E23N / 4, S23E, TT * E23N);
        }
        // ---- cell 23i: [h4e(t), h23e(t)] + hh h23i(t-1)
        {
            GArgs a;
            a.wt = wtp + OFF23I; a.N = I23N; a.S = S23I; a.partial = pp;
            a.act[0] = o4e;  a.ld[0] = TT * E4N;  a.len[0] = E4N;  a.seg4off[0] = 0;
            a.act[1] = o23e; a.ld[1] = TT * E23N; a.len[1] = E23N; a.seg4off[1] = 1200;
            a.act[2] = p23i; a.ld[2] = l23i;      a.len[2] = I23N; a.seg4off[2] = 2400;
            a.nseg = 3;
            gemvt_kernel<<<dim3(nbI, S23I), GBDIM>>>(a);
            reduce_kernel<<<(BB * I23N / 4 + 255) / 256, 256>>>(
                (const float4*)pp, (const float4*)bih23i, (const float4*)bhh23i,
                o23i, I23N / 4, S23I, TT * I23N);
        }
    }
    (void)in_sizes; (void)n_in; (void)out_size;
}